// round 11
// baseline (speedup 1.0000x reference)
#include <cuda_runtime.h>
#include <cstdint>
#include <cstddef>

#define B_ 4
#define L_ 512
#define D_ 256
#define H_ 128

// ---------------- scratch (device globals; no runtime allocation) ----------------
__device__ float g_own [B_*L_*H_];      // [2048,128]
__device__ float g_comp[B_*L_*H_];      // [2048,128]
__device__ float g_cat [B_*L_*2*D_];    // [2048,512]  concat(v, C)
__device__ float g_gate[B_*L_*2*D_];    // [2048,512]  gated input
__device__ float g_xpf [B_*L_*3*H_];    // [2048,384]
__device__ float g_xpb [B_*L_*3*H_];    // [2048,384]

// ---------------- helpers ----------------
__device__ __forceinline__ float tanh_fast(float x) {
    float y; asm("tanh.approx.f32 %0, %1;" : "=f"(y) : "f"(x)); return y;
}
// sigmoid(x) = 0.5*tanh(0.5x) + 0.5  -> single MUFU on the critical path
__device__ __forceinline__ float sigmoid_fast(float x) {
    return fmaf(0.5f, tanh_fast(0.5f * x), 0.5f);
}
__device__ __forceinline__ unsigned long long pack2f(float a, float b) {
    unsigned long long r; asm("mov.b64 %0, {%1, %2};" : "=l"(r) : "f"(a), "f"(b)); return r;
}
__device__ __forceinline__ unsigned long long fma2f(unsigned long long a, unsigned long long b, unsigned long long c) {
    unsigned long long d; asm("fma.rn.f32x2 %0, %1, %2, %3;" : "=l"(d) : "l"(a), "l"(b), "l"(c)); return d;
}
__device__ __forceinline__ unsigned long long add2f(unsigned long long a, unsigned long long b) {
    unsigned long long d; asm("add.rn.f32x2 %0, %1, %2;" : "=l"(d) : "l"(a), "l"(b)); return d;
}
__device__ __forceinline__ float2 unpack2f(unsigned long long a) {
    float x, y; asm("mov.b64 {%0, %1}, %2;" : "=f"(x), "=f"(y) : "l"(a));
    return make_float2(x, y);
}

// ---------------- packed-f32x2 GEMM, 64x128 tile, 4m x 8n per thread ----------------
// C[m,n] = act(A[m,:K] . W[n,:K] + bias[n]).   k-tile = 8, double buffered.
// A stored DUPLICATED as u64 (a,a); W stored plain float, read as (w0,w1) pairs.
// Per kk per thread: 6 LDS.128 (96B) feed 16 FFMA2 (32 FMA lanes) -> crossbar no longer binding.
// blockIdx.z selects weight/bias/output set (fused twin launches).
// EPI 0: +bias.  EPI 1: sigmoid(acc+bias) * mul[m,n]   (gating; N == K)
template<int EPI>
__global__ void __launch_bounds__(256) gemm8_kernel(
    const float* __restrict__ A,
    const float* __restrict__ W0, const float* __restrict__ W1,
    const float* __restrict__ bias0, const float* __restrict__ bias1,
    const float* __restrict__ mul,
    float* __restrict__ C0, float* __restrict__ C1,
    int M, int N, int K)
{
    __shared__ __align__(16) unsigned long long As2[2][8][64];  // dup'd A: (kk, m)
    __shared__ __align__(16) float              Ws [2][8][128]; // plain W: (kk, n)

    const float* W    = blockIdx.z ? W1 : W0;
    const float* bias = blockIdx.z ? bias1 : bias0;
    float*       C    = blockIdx.z ? C1 : C0;

    const int m0 = blockIdx.y * 64, n0 = blockIdx.x * 128;
    const int tid = threadIdx.x;
    const int tx = tid & 15, ty = tid >> 4;         // compute map: 4m x 8n
    const int lrow = tid >> 1, lkq = (tid & 1) * 4; // loader map
    const int KT = K >> 3;

    const float* Wrow = W + (size_t)(n0 + lrow) * K + lkq;                 // all 256 thr
    const float* Arow = (tid < 128) ? (A + (size_t)(m0 + lrow) * K + lkq)  // first 128 thr
                                    : nullptr;

    // prologue: tile 0
    {
        float4 wv = *(const float4*)Wrow;
        Ws[0][lkq+0][lrow] = wv.x; Ws[0][lkq+1][lrow] = wv.y;
        Ws[0][lkq+2][lrow] = wv.z; Ws[0][lkq+3][lrow] = wv.w;
        if (tid < 128) {
            float4 av = *(const float4*)Arow;
            As2[0][lkq+0][lrow] = pack2f(av.x, av.x);
            As2[0][lkq+1][lrow] = pack2f(av.y, av.y);
            As2[0][lkq+2][lrow] = pack2f(av.z, av.z);
            As2[0][lkq+3][lrow] = pack2f(av.w, av.w);
        }
    }
    __syncthreads();

    unsigned long long acc[4][4];
    #pragma unroll
    for (int i = 0; i < 4; i++)
        #pragma unroll
        for (int j = 0; j < 4; j++) acc[i][j] = 0ull;

    int cur = 0;
    for (int kt = 0; kt < KT; kt++) {
        float4 av, wv;
        const bool more = (kt + 1 < KT);
        if (more) {
            wv = *(const float4*)(Wrow + (kt + 1) * 8);
            if (tid < 128) av = *(const float4*)(Arow + (kt + 1) * 8);
        }
        #pragma unroll
        for (int kk = 0; kk < 8; kk++) {
            ulonglong2 aq0 = *(const ulonglong2*)&As2[cur][kk][ty * 4];
            ulonglong2 aq1 = *(const ulonglong2*)&As2[cur][kk][ty * 4 + 2];
            ulonglong2 wp0 = *(const ulonglong2*)&Ws[cur][kk][tx * 8];
            ulonglong2 wp1 = *(const ulonglong2*)&Ws[cur][kk][tx * 8 + 4];
            acc[0][0] = fma2f(aq0.x, wp0.x, acc[0][0]);
            acc[0][1] = fma2f(aq0.x, wp0.y, acc[0][1]);
            acc[0][2] = fma2f(aq0.x, wp1.x, acc[0][2]);
            acc[0][3] = fma2f(aq0.x, wp1.y, acc[0][3]);
            acc[1][0] = fma2f(aq0.y, wp0.x, acc[1][0]);
            acc[1][1] = fma2f(aq0.y, wp0.y, acc[1][1]);
            acc[1][2] = fma2f(aq0.y, wp1.x, acc[1][2]);
            acc[1][3] = fma2f(aq0.y, wp1.y, acc[1][3]);
            acc[2][0] = fma2f(aq1.x, wp0.x, acc[2][0]);
            acc[2][1] = fma2f(aq1.x, wp0.y, acc[2][1]);
            acc[2][2] = fma2f(aq1.x, wp1.x, acc[2][2]);
            acc[2][3] = fma2f(aq1.x, wp1.y, acc[2][3]);
            acc[3][0] = fma2f(aq1.y, wp0.x, acc[3][0]);
            acc[3][1] = fma2f(aq1.y, wp0.y, acc[3][1]);
            acc[3][2] = fma2f(aq1.y, wp1.x, acc[3][2]);
            acc[3][3] = fma2f(aq1.y, wp1.y, acc[3][3]);
        }
        if (more) {
            int nb = cur ^ 1;
            Ws[nb][lkq+0][lrow] = wv.x; Ws[nb][lkq+1][lrow] = wv.y;
            Ws[nb][lkq+2][lrow] = wv.z; Ws[nb][lkq+3][lrow] = wv.w;
            if (tid < 128) {
                As2[nb][lkq+0][lrow] = pack2f(av.x, av.x);
                As2[nb][lkq+1][lrow] = pack2f(av.y, av.y);
                As2[nb][lkq+2][lrow] = pack2f(av.z, av.z);
                As2[nb][lkq+3][lrow] = pack2f(av.w, av.w);
            }
            __syncthreads();
            cur = nb;
        }
    }

    #pragma unroll
    for (int i = 0; i < 4; i++) {
        const int m = m0 + ty * 4 + i;
        float vals[8];
        #pragma unroll
        for (int j = 0; j < 4; j++) {
            float2 p = unpack2f(acc[i][j]);
            vals[2*j] = p.x; vals[2*j+1] = p.y;
        }
        float4 r0, r1;
        float* rv0 = (float*)&r0; float* rv1 = (float*)&r1;
        #pragma unroll
        for (int j = 0; j < 4; j++) {
            int n = n0 + tx * 8 + j;
            float val = vals[j] + bias[n];
            if (EPI == 1) val = sigmoid_fast(val) * mul[(size_t)m * N + n];
            rv0[j] = val;
        }
        #pragma unroll
        for (int j = 0; j < 4; j++) {
            int n = n0 + tx * 8 + 4 + j;
            float val = vals[4 + j] + bias[n];
            if (EPI == 1) val = sigmoid_fast(val) * mul[(size_t)m * N + n];
            rv1[j] = val;
        }
        *(float4*)&C[(size_t)m * N + n0 + tx * 8]     = r0;
        *(float4*)&C[(size_t)m * N + n0 + tx * 8 + 4] = r1;
    }
}

// ---------------- attention: scores(tanh) -> softmax -> context, writes concat(v,C) ----------------
// grid (L/8, B), 256 threads. warp w owns query row q0+w. Key tiles beyond len skipped.
__global__ void __launch_bounds__(256) attn_kernel(
    const float* __restrict__ v, const float* __restrict__ own,
    const float* __restrict__ comp, const float* __restrict__ va,
    const int* __restrict__ lengths, float* __restrict__ cat)
{
    __shared__ float own_s[8 * 128];
    __shared__ float va_s[128];
    __shared__ float scores[8 * 512];
    __shared__ __align__(16) float tile[32 * 132];   // union: comp tile (32x132) / v tile (16x256)
    const int b  = blockIdx.y;
    const int q0 = blockIdx.x * 8;
    const int tid = threadIdx.x;
    const int len = lengths[b];
    const size_t base = (size_t)b * L_;

    for (int i = tid; i < (8 * 128) / 4; i += 256)
        ((float4*)own_s)[i] = ((const float4*)(own + (base + q0) * H_))[i];
    if (tid < 128) va_s[tid] = va[tid];

    const int klane = tid & 31, qw = tid >> 5;

    // ---- pass 1: scores[q, k] = sum_h va[h] * tanh(own[q,h] + comp[k,h]); only k-tiles < len ----
    const int kt1 = (len + 31) >> 5;
    for (int kt = 0; kt < kt1; kt++) {
        __syncthreads();
        for (int i = tid; i < 1024; i += 256) {              // 32 rows x 32 float4
            int kk = i >> 5, hq = i & 31;
            float4 cv = *(const float4*)&comp[(base + kt * 32 + kk) * H_ + hq * 4];
            *(float4*)&tile[kk * 132 + hq * 4] = cv;
        }
        __syncthreads();
        const float* orow = own_s + qw * 128;
        const float* crow = tile + klane * 132;
        float s = 0.f;
        #pragma unroll
        for (int h = 0; h < 128; h += 4) {
            float4 ov = *(const float4*)&orow[h];
            float4 cv = *(const float4*)&crow[h];
            float4 vv = *(const float4*)&va_s[h];
            s += vv.x * tanh_fast(ov.x + cv.x);
            s += vv.y * tanh_fast(ov.y + cv.y);
            s += vv.z * tanh_fast(ov.z + cv.z);
            s += vv.w * tanh_fast(ov.w + cv.w);
        }
        scores[qw * 512 + kt * 32 + klane] = s;
    }
    __syncthreads();

    // ---- softmax over k (masked at k >= len); warp qw owns row qw ----
    {
        float* row = scores + qw * 512;
        float sv[16];
        float mx = -3.0e38f;
        #pragma unroll
        for (int i = 0; i < 16; i++) {
            int k = klane + i * 32;
            sv[i] = (k < len) ? row[k] : -3.0e38f;
            mx = fmaxf(mx, sv[i]);
        }
        #pragma unroll
        for (int off = 16; off; off >>= 1) mx = fmaxf(mx, __shfl_xor_sync(0xffffffffu, mx, off));
        float sum = 0.f;
        #pragma unroll
        for (int i = 0; i < 16; i++) {
            int k = klane + i * 32;
            float e = (k < len) ? __expf(sv[i] - mx) : 0.f;
            sv[i] = e; sum += e;
        }
        #pragma unroll
        for (int off = 16; off; off >>= 1) sum += __shfl_xor_sync(0xffffffffu, sum, off);
        float inv = __fdividef(1.f, sum);
        #pragma unroll
        for (int i = 0; i < 16; i++) row[klane + i * 32] = sv[i] * inv;
    }
    __syncthreads();

    // ---- pass 2: C[q, d] = sum_k attn[q,k] * v[k,d]; only k-tiles < len (attn==0 beyond) ----
    float acc[8] = {};
    const int dg = tid & 31;
    const int kt2 = (len + 15) >> 4;
    for (int kt = 0; kt < kt2; kt++) {
        __syncthreads();
        for (int i = tid; i < 1024; i += 256) {              // 16 rows x 64 float4
            int kk = i >> 6, dq = i & 63;
            *(float4*)&tile[kk * 256 + dq * 4] = *(const float4*)&v[(base + kt * 16 + kk) * D_ + dq * 4];
        }
        __syncthreads();
        #pragma unroll 4
        for (int kk = 0; kk < 16; kk++) {
            float a = scores[qw * 512 + kt * 16 + kk];
            float4 lo = *(const float4*)&tile[kk * 256 + dg * 4];
            float4 hi = *(const float4*)&tile[kk * 256 + 128 + dg * 4];
            acc[0] += a * lo.x; acc[1] += a * lo.y; acc[2] += a * lo.z; acc[3] += a * lo.w;
            acc[4] += a * hi.x; acc[5] += a * hi.y; acc[6] += a * hi.z; acc[7] += a * hi.w;
        }
    }
    {
        size_t m = base + q0 + qw;
        float4 o1 = make_float4(acc[0], acc[1], acc[2], acc[3]);
        float4 o2 = make_float4(acc[4], acc[5], acc[6], acc[7]);
        *(float4*)&cat[m * 512 + 256 + dg * 4] = o1;
        *(float4*)&cat[m * 512 + 384 + dg * 4] = o2;
    }
    // copy v into cat[:, 0:256]
    for (int i = tid; i < 512; i += 256) {
        int qq = i >> 6, dq = i & 63;
        size_t m = base + q0 + qq;
        *(float4*)&cat[m * 512 + dq * 4] = *(const float4*)&v[m * D_ + dq * 4];
    }
}

// ---------------- GRU recurrence: one CTA per (batch, direction); w_hh rows in registers ----------------
// Only `len` real steps per batch (masked region has h=0, out=0: trailing for fwd, leading for bwd);
// the invalid region is bulk zero-filled.
__global__ void __launch_bounds__(384, 1) gru_kernel(
    const float* __restrict__ xpf, const float* __restrict__ xpb,
    const float* __restrict__ whhf, const float* __restrict__ whhb,
    const float* __restrict__ bhhf, const float* __restrict__ bhhb,
    const int* __restrict__ lengths, float* __restrict__ out)
{
    const int b   = blockIdx.x & 3;
    const int dir = blockIdx.x >> 2;
    const float* xp  = dir ? xpb  : xpf;
    const float* whh = dir ? whhb : whhf;
    const float* bhh = dir ? bhhb : bhhf;
    const int o = threadIdx.x;           // 0..383 : output index of hp
    const int len = lengths[b];

    __shared__ __align__(16) float h_s[128];
    __shared__ float hp_s[384];
    __shared__ float xp_s[384];

    // w_hh row of this output, packed into f32x2 registers (128 floats -> 64 u64 regs)
    unsigned long long w2[64];
    {
        const float4* wr = (const float4*)(whh + (size_t)o * 128);
        #pragma unroll
        for (int j = 0; j < 32; j++) {
            float4 t = wr[j];
            w2[2 * j]     = pack2f(t.x, t.y);
            w2[2 * j + 1] = pack2f(t.z, t.w);
        }
    }
    const float bo = bhh[o];
    if (o < 128) h_s[o] = 0.f;

    const size_t xbase = (size_t)b * L_ * 384;
    const size_t obase = (size_t)b * L_ * 256 + (size_t)dir * 128;

    // bulk zero-fill of the invalid region [len, L)
    for (int i = o; i < (L_ - len) * 128; i += 384) {
        int t = len + (i >> 7);
        out[obase + (size_t)t * 256 + (i & 127)] = 0.f;
    }
    __syncthreads();

    for (int s = 0; s < len; s++) {
        const int t = dir ? (len - 1 - s) : s;
        const float xv = xp[xbase + (size_t)t * 384 + o];   // issued early, hidden under matvec

        // 8 accumulator chains (shallow dependency depth)
        unsigned long long a[8];
        #pragma unroll
        for (int c = 0; c < 8; c++) a[c] = 0ull;
        const ulonglong2* h4 = (const ulonglong2*)h_s;
        #pragma unroll
        for (int j = 0; j < 8; j++) {
            ulonglong2 hA = h4[4 * j];
            ulonglong2 hB = h4[4 * j + 1];
            ulonglong2 hC = h4[4 * j + 2];
            ulonglong2 hD = h4[4 * j + 3];
            a[0] = fma2f(w2[8 * j + 0], hA.x, a[0]);
            a[1] = fma2f(w2[8 * j + 1], hA.y, a[1]);
            a[2] = fma2f(w2[8 * j + 2], hB.x, a[2]);
            a[3] = fma2f(w2[8 * j + 3], hB.y, a[3]);
            a[4] = fma2f(w2[8 * j + 4], hC.x, a[4]);
            a[5] = fma2f(w2[8 * j + 5], hC.y, a[5]);
            a[6] = fma2f(w2[8 * j + 6], hD.x, a[6]);
            a[7] = fma2f(w2[8 * j + 7], hD.y, a[7]);
        }
        a[0] = add2f(a[0], a[1]); a[2] = add2f(a[2], a[3]);
        a[4] = add2f(a[4], a[5]); a[6] = add2f(a[6], a[7]);
        a[0] = add2f(a[0], a[2]); a[4] = add2f(a[4], a[6]);
        a[0] = add2f(a[0], a[4]);
        float2 f = unpack2f(a[0]);
        hp_s[o] = bo + f.x + f.y;
        xp_s[o] = xv;
        __syncthreads();

        if (o < 128) {
            float r = sigmoid_fast(xp_s[o]       + hp_s[o]);
            float z = sigmoid_fast(xp_s[128 + o] + hp_s[128 + o]);
            float n = tanh_fast  (xp_s[256 + o] + r * hp_s[256 + o]);
            float hn = (1.f - z) * n + z * h_s[o];
            out[obase + (size_t)t * 256 + o] = hn;
            h_s[o] = hn;
        }
        __syncthreads();
    }
}

// ---------------- launch ----------------
extern "C" void kernel_launch(void* const* d_in, const int* in_sizes, int n_in,
                              void* d_out, int out_size)
{
    (void)in_sizes; (void)n_in; (void)out_size;
    const float* v       = (const float*)d_in[0];
    const int*   lengths = (const int*)  d_in[1];
    // d_in[2] = p_mask (bool) — recomputed from lengths, unused.
    const float* own_W   = (const float*)d_in[3];
    const float* own_b   = (const float*)d_in[4];
    const float* comp_W  = (const float*)d_in[5];
    const float* comp_b  = (const float*)d_in[6];
    const float* v_attn  = (const float*)d_in[7];
    const float* gate_W  = (const float*)d_in[8];
    const float* gate_b  = (const float*)d_in[9];
    const float* w_ih_f  = (const float*)d_in[10];
    const float* w_hh_f  = (const float*)d_in[11];
    const float* b_ih_f  = (const float*)d_in[12];
    const float* b_hh_f  = (const float*)d_in[13];
    const float* w_ih_b  = (const float*)d_in[14];
    const float* w_hh_b  = (const float*)d_in[15];
    const float* b_ih_b  = (const float*)d_in[16];
    const float* b_hh_b  = (const float*)d_in[17];
    float* out = (float*)d_out;

    float *p_own, *p_comp, *p_cat, *p_g, *p_xpf, *p_xpb;
    cudaGetSymbolAddress((void**)&p_own,  g_own);
    cudaGetSymbolAddress((void**)&p_comp, g_comp);
    cudaGetSymbolAddress((void**)&p_cat,  g_cat);
    cudaGetSymbolAddress((void**)&p_g,    g_gate);
    cudaGetSymbolAddress((void**)&p_xpf,  g_xpf);
    cudaGetSymbolAddress((void**)&p_xpb,  g_xpb);

    const int M = B_ * L_;  // 2048

    // own + comp projections fused (z selects): [2048,256] x [128,256]^T -> 64 CTAs
    gemm8_kernel<0><<<dim3(128 / 128, M / 64, 2), 256>>>(
        v, own_W, comp_W, own_b, comp_b, nullptr, p_own, p_comp, M, 128, 256);

    // attention + context -> concat(v, C)
    attn_kernel<<<dim3(L_ / 8, B_), 256>>>(v, p_own, p_comp, v_attn, lengths, p_cat);

    // gating: g = sigmoid(cat @ gate_W^T + b) * cat -> 128 CTAs
    gemm8_kernel<1><<<dim3(512 / 128, M / 64, 1), 256>>>(
        p_cat, gate_W, gate_W, gate_b, gate_b, p_cat, p_g, p_g, M, 512, 512);

    // GRU input projections, both directions fused (z selects) -> 192 CTAs
    gemm8_kernel<0><<<dim3(384 / 128, M / 64, 2), 256>>>(
        p_g, w_ih_f, w_ih_b, b_ih_f, b_ih_b, nullptr, p_xpf, p_xpb, M, 384, 512);

    // sequential recurrence: 8 CTAs = 4 batches x 2 directions
    gru_kernel<<<8, 384>>>(p_xpf, p_xpb, w_hh_f, w_hh_b, b_hh_f, b_hh_b, lengths, out);
}

// round 16
// speedup vs baseline: 1.2586x; 1.2586x over previous
#include <cuda_runtime.h>
#include <cstdint>
#include <cstddef>

#define B_ 4
#define L_ 512
#define D_ 256
#define H_ 128

// ---------------- scratch (device globals; no runtime allocation) ----------------
__device__ float g_own [B_*L_*H_];      // [2048,128]
__device__ float g_comp[B_*L_*H_];      // [2048,128]
__device__ float g_cat [B_*L_*2*D_];    // [2048,512]  concat(v, C)
__device__ float g_gate[B_*L_*2*D_];    // [2048,512]  gated input
__device__ float g_xpf [B_*L_*3*H_];    // [2048,384]
__device__ float g_xpb [B_*L_*3*H_];    // [2048,384]

// ---------------- helpers ----------------
__device__ __forceinline__ float tanh_fast(float x) {
    float y; asm("tanh.approx.f32 %0, %1;" : "=f"(y) : "f"(x)); return y;
}
__device__ __forceinline__ float sigmoid_fast(float x) {
    return fmaf(0.5f, tanh_fast(0.5f * x), 0.5f);
}
__device__ __forceinline__ unsigned long long pack2f(float a, float b) {
    unsigned long long r; asm("mov.b64 %0, {%1, %2};" : "=l"(r) : "f"(a), "f"(b)); return r;
}
__device__ __forceinline__ unsigned long long fma2f(unsigned long long a, unsigned long long b, unsigned long long c) {
    unsigned long long d; asm("fma.rn.f32x2 %0, %1, %2, %3;" : "=l"(d) : "l"(a), "l"(b), "l"(c)); return d;
}
__device__ __forceinline__ unsigned long long add2f(unsigned long long a, unsigned long long b) {
    unsigned long long d; asm("add.rn.f32x2 %0, %1, %2;" : "=l"(d) : "l"(a), "l"(b)); return d;
}
__device__ __forceinline__ float2 unpack2f(unsigned long long a) {
    float x, y; asm("mov.b64 {%0, %1}, %2;" : "=f"(x), "=f"(y) : "l"(a));
    return make_float2(x, y);
}
__device__ __forceinline__ unsigned tf32_of(float f) {
    unsigned u; asm("cvt.rna.tf32.f32 %0, %1;" : "=r"(u) : "f"(f)); return u;
}
__device__ __forceinline__ void mma_tf32(float d[4], const unsigned a[4], const unsigned b[2]) {
    asm volatile(
        "mma.sync.aligned.m16n8k8.row.col.f32.tf32.tf32.f32 "
        "{%0,%1,%2,%3}, {%4,%5,%6,%7}, {%8,%9}, {%0,%1,%2,%3};"
        : "+f"(d[0]), "+f"(d[1]), "+f"(d[2]), "+f"(d[3])
        : "r"(a[0]), "r"(a[1]), "r"(a[2]), "r"(a[3]), "r"(b[0]), "r"(b[1]));
}

// ---------------- tf32 tensor-core GEMM: C[m,n] = act(A[m,:K] . W[n,:K] + bias[n]) ----------------
// CTA tile 128m x 64n, 256 threads (8 warps, warp tile 32x32). K-chunk 32.
// SMEM k-major with padded stride (%32==8) -> conflict-free fragment LDS and transposed STS.
// blockIdx.z selects weight/bias/output set (fused twin launches).
// EPI 0: +bias.  EPI 1: sigmoid(acc+bias) * mul[m,n]   (gating; N == K)
#define ASTR 136
#define WSTR 72
template<int EPI>
__global__ void __launch_bounds__(256) gemmtc_kernel(
    const float* __restrict__ A,
    const float* __restrict__ W0, const float* __restrict__ W1,
    const float* __restrict__ bias0, const float* __restrict__ bias1,
    const float* __restrict__ mul,
    float* __restrict__ C0, float* __restrict__ C1,
    int M, int N, int K)
{
    __shared__ unsigned As[32][ASTR];   // [k][m], tf32 bits
    __shared__ unsigned Ws[32][WSTR];   // [k][n], tf32 bits

    const float* W    = blockIdx.z ? W1 : W0;
    const float* bias = blockIdx.z ? bias1 : bias0;
    float*       C    = blockIdx.z ? C1 : C0;

    const int m0 = blockIdx.y * 128, n0 = blockIdx.x * 64;
    const int t = threadIdx.x;
    const int lane = t & 31, warp = t >> 5;
    const int wm = warp & 3, wn = warp >> 2;           // warp grid 4m x 2n
    const int tig = lane & 3, gid = lane >> 2;
    const int KT = K >> 5;                              // 32-wide k chunks

    // loader mapping
    const int la_m = t & 127, la_kh = (t >> 7) * 16;    // A: 128 rows x 2 k-halves
    const int lw_n = t & 63,  lw_kh = ((t >> 6) & 3) * 8; // W: 64 rows x 4 k-eighths
    const float* Ap = A + (size_t)(m0 + la_m) * K + la_kh;
    const float* Wp = W + (size_t)(n0 + lw_n) * K + lw_kh;

    float4 av[4], wv[2];
    #pragma unroll
    for (int q = 0; q < 4; q++) av[q] = *(const float4*)(Ap + q * 4);
    #pragma unroll
    for (int q = 0; q < 2; q++) wv[q] = *(const float4*)(Wp + q * 4);

    float acc[2][4][4];
    #pragma unroll
    for (int i = 0; i < 2; i++)
        #pragma unroll
        for (int j = 0; j < 4; j++)
            #pragma unroll
            for (int r = 0; r < 4; r++) acc[i][j][r] = 0.f;

    for (int c = 0; c < KT; c++) {
        if (c) __syncthreads();
        // transposed STS (lane-consecutive columns -> conflict-free)
        #pragma unroll
        for (int q = 0; q < 4; q++) {
            const float* f = (const float*)&av[q];
            #pragma unroll
            for (int e = 0; e < 4; e++)
                As[la_kh + q * 4 + e][la_m] = tf32_of(f[e]);
        }
        #pragma unroll
        for (int q = 0; q < 2; q++) {
            const float* f = (const float*)&wv[q];
            #pragma unroll
            for (int e = 0; e < 4; e++)
                Ws[lw_kh + q * 4 + e][lw_n] = tf32_of(f[e]);
        }
        __syncthreads();
        if (c + 1 < KT) {
            #pragma unroll
            for (int q = 0; q < 4; q++) av[q] = *(const float4*)(Ap + (c + 1) * 32 + q * 4);
            #pragma unroll
            for (int q = 0; q < 2; q++) wv[q] = *(const float4*)(Wp + (c + 1) * 32 + q * 4);
        }
        #pragma unroll
        for (int k8 = 0; k8 < 4; k8++) {
            const int kb = k8 * 8;
            unsigned afr[2][4];
            #pragma unroll
            for (int i = 0; i < 2; i++) {
                const int row = wm * 32 + i * 16 + gid;
                afr[i][0] = As[kb + tig][row];
                afr[i][1] = As[kb + tig][row + 8];
                afr[i][2] = As[kb + 4 + tig][row];
                afr[i][3] = As[kb + 4 + tig][row + 8];
            }
            unsigned bfr[4][2];
            #pragma unroll
            for (int j = 0; j < 4; j++) {
                const int col = wn * 32 + j * 8 + gid;
                bfr[j][0] = Ws[kb + tig][col];
                bfr[j][1] = Ws[kb + 4 + tig][col];
            }
            #pragma unroll
            for (int i = 0; i < 2; i++)
                #pragma unroll
                for (int j = 0; j < 4; j++)
                    mma_tf32(acc[i][j], afr[i], bfr[j]);
        }
    }

    // epilogue: d0,d1 -> (row, 2*tig..+1); d2,d3 -> (row+8, same cols)
    #pragma unroll
    for (int i = 0; i < 2; i++) {
        #pragma unroll
        for (int j = 0; j < 4; j++) {
            const int m_lo = m0 + wm * 32 + i * 16 + gid;
            const int m_hi = m_lo + 8;
            const int n_c  = n0 + wn * 32 + j * 8 + tig * 2;
            float b0v = bias[n_c], b1v = bias[n_c + 1];
            float v0 = acc[i][j][0] + b0v;
            float v1 = acc[i][j][1] + b1v;
            float v2 = acc[i][j][2] + b0v;
            float v3 = acc[i][j][3] + b1v;
            if (EPI == 1) {
                float2 mlo = *(const float2*)&mul[(size_t)m_lo * N + n_c];
                float2 mhi = *(const float2*)&mul[(size_t)m_hi * N + n_c];
                v0 = sigmoid_fast(v0) * mlo.x;
                v1 = sigmoid_fast(v1) * mlo.y;
                v2 = sigmoid_fast(v2) * mhi.x;
                v3 = sigmoid_fast(v3) * mhi.y;
            }
            *(float2*)&C[(size_t)m_lo * N + n_c] = make_float2(v0, v1);
            *(float2*)&C[(size_t)m_hi * N + n_c] = make_float2(v2, v3);
        }
    }
}

// ---------------- attention: scores(tanh) -> softmax -> context, writes concat(v,C) ----------------
// grid (L/8, B), 256 threads. warp w owns query row q0+w. Key tiles beyond len skipped.
__global__ void __launch_bounds__(256) attn_kernel(
    const float* __restrict__ v, const float* __restrict__ own,
    const float* __restrict__ comp, const float* __restrict__ va,
    const int* __restrict__ lengths, float* __restrict__ cat)
{
    __shared__ float own_s[8 * 128];
    __shared__ float va_s[128];
    __shared__ float scores[8 * 512];
    __shared__ __align__(16) float tile[32 * 132];   // union: comp tile (32x132) / v tile (16x256)
    const int b  = blockIdx.y;
    const int q0 = blockIdx.x * 8;
    const int tid = threadIdx.x;
    const int len = lengths[b];
    const size_t base = (size_t)b * L_;

    for (int i = tid; i < (8 * 128) / 4; i += 256)
        ((float4*)own_s)[i] = ((const float4*)(own + (base + q0) * H_))[i];
    if (tid < 128) va_s[tid] = va[tid];

    const int klane = tid & 31, qw = tid >> 5;

    // ---- pass 1: scores[q, k] = sum_h va[h] * tanh(own[q,h] + comp[k,h]); only k-tiles < len ----
    const int kt1 = (len + 31) >> 5;
    for (int kt = 0; kt < kt1; kt++) {
        __syncthreads();
        for (int i = tid; i < 1024; i += 256) {              // 32 rows x 32 float4
            int kk = i >> 5, hq = i & 31;
            float4 cv = *(const float4*)&comp[(base + kt * 32 + kk) * H_ + hq * 4];
            *(float4*)&tile[kk * 132 + hq * 4] = cv;
        }
        __syncthreads();
        const float* orow = own_s + qw * 128;
        const float* crow = tile + klane * 132;
        float s = 0.f;
        #pragma unroll
        for (int h = 0; h < 128; h += 4) {
            float4 ov = *(const float4*)&orow[h];
            float4 cv = *(const float4*)&crow[h];
            float4 vv = *(const float4*)&va_s[h];
            s += vv.x * tanh_fast(ov.x + cv.x);
            s += vv.y * tanh_fast(ov.y + cv.y);
            s += vv.z * tanh_fast(ov.z + cv.z);
            s += vv.w * tanh_fast(ov.w + cv.w);
        }
        scores[qw * 512 + kt * 32 + klane] = s;
    }
    __syncthreads();

    // ---- softmax over k (masked at k >= len); warp qw owns row qw ----
    {
        float* row = scores + qw * 512;
        float sv[16];
        float mx = -3.0e38f;
        #pragma unroll
        for (int i = 0; i < 16; i++) {
            int k = klane + i * 32;
            sv[i] = (k < len) ? row[k] : -3.0e38f;
            mx = fmaxf(mx, sv[i]);
        }
        #pragma unroll
        for (int off = 16; off; off >>= 1) mx = fmaxf(mx, __shfl_xor_sync(0xffffffffu, mx, off));
        float sum = 0.f;
        #pragma unroll
        for (int i = 0; i < 16; i++) {
            int k = klane + i * 32;
            float e = (k < len) ? __expf(sv[i] - mx) : 0.f;
            sv[i] = e; sum += e;
        }
        #pragma unroll
        for (int off = 16; off; off >>= 1) sum += __shfl_xor_sync(0xffffffffu, sum, off);
        float inv = __fdividef(1.f, sum);
        #pragma unroll
        for (int i = 0; i < 16; i++) row[klane + i * 32] = sv[i] * inv;
    }
    __syncthreads();

    // ---- pass 2: C[q, d] = sum_k attn[q,k] * v[k,d]; only k-tiles < len (attn==0 beyond) ----
    float acc[8] = {};
    const int dg = tid & 31;
    const int kt2 = (len + 15) >> 4;
    for (int kt = 0; kt < kt2; kt++) {
        __syncthreads();
        for (int i = tid; i < 1024; i += 256) {              // 16 rows x 64 float4
            int kk = i >> 6, dq = i & 63;
            *(float4*)&tile[kk * 256 + dq * 4] = *(const float4*)&v[(base + kt * 16 + kk) * D_ + dq * 4];
        }
        __syncthreads();
        #pragma unroll 4
        for (int kk = 0; kk < 16; kk++) {
            float a = scores[qw * 512 + kt * 16 + kk];
            float4 lo = *(const float4*)&tile[kk * 256 + dg * 4];
            float4 hi = *(const float4*)&tile[kk * 256 + 128 + dg * 4];
            acc[0] += a * lo.x; acc[1] += a * lo.y; acc[2] += a * lo.z; acc[3] += a * lo.w;
            acc[4] += a * hi.x; acc[5] += a * hi.y; acc[6] += a * hi.z; acc[7] += a * hi.w;
        }
    }
    {
        size_t m = base + q0 + qw;
        float4 o1 = make_float4(acc[0], acc[1], acc[2], acc[3]);
        float4 o2 = make_float4(acc[4], acc[5], acc[6], acc[7]);
        *(float4*)&cat[m * 512 + 256 + dg * 4] = o1;
        *(float4*)&cat[m * 512 + 384 + dg * 4] = o2;
    }
    // copy v into cat[:, 0:256]
    for (int i = tid; i < 512; i += 256) {
        int qq = i >> 6, dq = i & 63;
        size_t m = base + q0 + qq;
        *(float4*)&cat[m * 512 + dq * 4] = *(const float4*)&v[m * D_ + dq * 4];
    }
}

// ---------------- GRU recurrence: one CTA per (batch, direction); w_hh rows in registers ----------------
__global__ void __launch_bounds__(384, 1) gru_kernel(
    const float* __restrict__ xpf, const float* __restrict__ xpb,
    const float* __restrict__ whhf, const float* __restrict__ whhb,
    const float* __restrict__ bhhf, const float* __restrict__ bhhb,
    const int* __restrict__ lengths, float* __restrict__ out)
{
    const int b   = blockIdx.x & 3;
    const int dir = blockIdx.x >> 2;
    const float* xp  = dir ? xpb  : xpf;
    const float* whh = dir ? whhb : whhf;
    const float* bhh = dir ? bhhb : bhhf;
    const int o = threadIdx.x;           // 0..383 : output index of hp
    const int len = lengths[b];

    __shared__ __align__(16) float h_s[128];
    __shared__ float hp_s[384];
    __shared__ float xp_s[384];

    unsigned long long w2[64];
    {
        const float4* wr = (const float4*)(whh + (size_t)o * 128);
        #pragma unroll
        for (int j = 0; j < 32; j++) {
            float4 t = wr[j];
            w2[2 * j]     = pack2f(t.x, t.y);
            w2[2 * j + 1] = pack2f(t.z, t.w);
        }
    }
    const float bo = bhh[o];
    if (o < 128) h_s[o] = 0.f;

    const size_t xbase = (size_t)b * L_ * 384;
    const size_t obase = (size_t)b * L_ * 256 + (size_t)dir * 128;

    // bulk zero-fill of the invalid region [len, L)
    for (int i = o; i < (L_ - len) * 128; i += 384) {
        int t = len + (i >> 7);
        out[obase + (size_t)t * 256 + (i & 127)] = 0.f;
    }
    __syncthreads();

    for (int s = 0; s < len; s++) {
        const int t = dir ? (len - 1 - s) : s;
        const float xv = xp[xbase + (size_t)t * 384 + o];

        unsigned long long a[8];
        #pragma unroll
        for (int c = 0; c < 8; c++) a[c] = 0ull;
        const ulonglong2* h4 = (const ulonglong2*)h_s;
        #pragma unroll
        for (int j = 0; j < 8; j++) {
            ulonglong2 hA = h4[4 * j];
            ulonglong2 hB = h4[4 * j + 1];
            ulonglong2 hC = h4[4 * j + 2];
            ulonglong2 hD = h4[4 * j + 3];
            a[0] = fma2f(w2[8 * j + 0], hA.x, a[0]);
            a[1] = fma2f(w2[8 * j + 1], hA.y, a[1]);
            a[2] = fma2f(w2[8 * j + 2], hB.x, a[2]);
            a[3] = fma2f(w2[8 * j + 3], hB.y, a[3]);
            a[4] = fma2f(w2[8 * j + 4], hC.x, a[4]);
            a[5] = fma2f(w2[8 * j + 5], hC.y, a[5]);
            a[6] = fma2f(w2[8 * j + 6], hD.x, a[6]);
            a[7] = fma2f(w2[8 * j + 7], hD.y, a[7]);
        }
        a[0] = add2f(a[0], a[1]); a[2] = add2f(a[2], a[3]);
        a[4] = add2f(a[4], a[5]); a[6] = add2f(a[6], a[7]);
        a[0] = add2f(a[0], a[2]); a[4] = add2f(a[4], a[6]);
        a[0] = add2f(a[0], a[4]);
        float2 f = unpack2f(a[0]);
        hp_s[o] = bo + f.x + f.y;
        xp_s[o] = xv;
        __syncthreads();

        if (o < 128) {
            float r = sigmoid_fast(xp_s[o]       + hp_s[o]);
            float z = sigmoid_fast(xp_s[128 + o] + hp_s[128 + o]);
            float n = tanh_fast  (xp_s[256 + o] + r * hp_s[256 + o]);
            float hn = (1.f - z) * n + z * h_s[o];
            out[obase + (size_t)t * 256 + o] = hn;
            h_s[o] = hn;
        }
        __syncthreads();
    }
}

// ---------------- launch ----------------
extern "C" void kernel_launch(void* const* d_in, const int* in_sizes, int n_in,
                              void* d_out, int out_size)
{
    (void)in_sizes; (void)n_in; (void)out_size;
    const float* v       = (const float*)d_in[0];
    const int*   lengths = (const int*)  d_in[1];
    // d_in[2] = p_mask (bool) — recomputed from lengths, unused.
    const float* own_W   = (const float*)d_in[3];
    const float* own_b   = (const float*)d_in[4];
    const float* comp_W  = (const float*)d_in[5];
    const float* comp_b  = (const float*)d_in[6];
    const float* v_attn  = (const float*)d_in[7];
    const float* gate_W  = (const float*)d_in[8];
    const float* gate_b  = (const float*)d_in[9];
    const float* w_ih_f  = (const float*)d_in[10];
    const float* w_hh_f  = (const float*)d_in[11];
    const float* b_ih_f  = (const float*)d_in[12];
    const float* b_hh_f  = (const float*)d_in[13];
    const float* w_ih_b  = (const float*)d_in[14];
    const float* w_hh_b  = (const float*)d_in[15];
    const float* b_ih_b  = (const float*)d_in[16];
    const float* b_hh_b  = (const float*)d_in[17];
    float* out = (float*)d_out;

    float *p_own, *p_comp, *p_cat, *p_g, *p_xpf, *p_xpb;
    cudaGetSymbolAddress((void**)&p_own,  g_own);
    cudaGetSymbolAddress((void**)&p_comp, g_comp);
    cudaGetSymbolAddress((void**)&p_cat,  g_cat);
    cudaGetSymbolAddress((void**)&p_g,    g_gate);
    cudaGetSymbolAddress((void**)&p_xpf,  g_xpf);
    cudaGetSymbolAddress((void**)&p_xpb,  g_xpb);

    const int M = B_ * L_;  // 2048

    // own + comp projections fused (z selects): [2048,256] x [128,256]^T -> 64 CTAs
    gemmtc_kernel<0><<<dim3(128 / 64, M / 128, 2), 256>>>(
        v, own_W, comp_W, own_b, comp_b, nullptr, p_own, p_comp, M, 128, 256);

    // attention + context -> concat(v, C)
    attn_kernel<<<dim3(L_ / 8, B_), 256>>>(v, p_own, p_comp, v_attn, lengths, p_cat);

    // gating: g = sigmoid(cat @ gate_W^T + b) * cat -> 128 CTAs
    gemmtc_kernel<1><<<dim3(512 / 64, M / 128, 1), 256>>>(
        p_cat, gate_W, gate_W, gate_b, gate_b, p_cat, p_g, p_g, M, 512, 512);

    // GRU input projections, both directions fused (z selects) -> 192 CTAs
    gemmtc_kernel<0><<<dim3(384 / 64, M / 128, 2), 256>>>(
        p_g, w_ih_f, w_ih_b, b_ih_f, b_ih_b, nullptr, p_xpf, p_xpb, M, 384, 512);

    // sequential recurrence: 8 CTAs = 4 batches x 2 directions
    gru_kernel<<<8, 384>>>(p_xpf, p_xpb, w_hh_f, w_hh_b, b_hh_f, b_hh_b, lengths, out);
}